// round 12
// baseline (speedup 1.0000x reference)
#include <cuda_runtime.h>
#include <cuda_bf16.h>
#include <cstdint>

#define D  512
#define TT 128
#define NN 64
#define SS 128

// ---- scratch (static device globals; no allocation) ----
__device__ float g_P[8192 * 512];        // dec @ W0 + b_obj
__device__ float g_qproj[384 * 512];     // src_e[0:6] @ W_obj[1024:1536]
__device__ float g_embproj[6 * 512];
__device__ float g_embdir[6 * 5];
__device__ float g_qdir[384 * 5];
__device__ float g_rdir[384 * 5];
__device__ float g_part[2][64 * 128 * 128];  // split-K einsum partials [half][n][t][s]

// ================= warp-level tensor helpers (sm_80+ base-target) =================
__device__ __forceinline__ uint32_t smem_u32(const void* p) {
    uint32_t a;
    asm("{ .reg .u64 t; cvta.to.shared.u64 t, %1; cvt.u32.u64 %0, t; }" : "=r"(a) : "l"(p));
    return a;
}
__device__ __forceinline__ void ldsm_x4(uint32_t* r, uint32_t addr) {
    asm volatile("ldmatrix.sync.aligned.m8n8.x4.shared.b16 {%0,%1,%2,%3}, [%4];"
                 : "=r"(r[0]), "=r"(r[1]), "=r"(r[2]), "=r"(r[3]) : "r"(addr));
}
__device__ __forceinline__ void ldsm_x2(uint32_t* r, uint32_t addr) {
    asm volatile("ldmatrix.sync.aligned.m8n8.x2.shared.b16 {%0,%1}, [%2];"
                 : "=r"(r[0]), "=r"(r[1]) : "r"(addr));
}
__device__ __forceinline__ void ldsm_x2_t(uint32_t* r, uint32_t addr) {
    asm volatile("ldmatrix.sync.aligned.m8n8.x2.trans.shared.b16 {%0,%1}, [%2];"
                 : "=r"(r[0]), "=r"(r[1]) : "r"(addr));
}
__device__ __forceinline__ void mma16816(float* c, const uint32_t* a, const uint32_t* b) {
    asm volatile("mma.sync.aligned.m16n8k16.row.col.f32.bf16.bf16.f32 "
                 "{%0,%1,%2,%3}, {%4,%5,%6,%7}, {%8,%9}, {%0,%1,%2,%3};"
                 : "+f"(c[0]), "+f"(c[1]), "+f"(c[2]), "+f"(c[3])
                 : "r"(a[0]), "r"(a[1]), "r"(a[2]), "r"(a[3]), "r"(b[0]), "r"(b[1]));
}

// ---- fp32 -> bf16 hi/lo split helpers ----
__device__ __forceinline__ void split_sts8(const float* xs, char* dhi, char* dlo) {
    uint32_t hw[4], lw[4];
    #pragma unroll
    for (int p = 0; p < 4; p++) {
        float a = xs[2 * p], b = xs[2 * p + 1];
        __nv_bfloat162 hb2 = __floats2bfloat162_rn(a, b);
        float ha = __bfloat162float(__low2bfloat16(hb2));
        float hbv = __bfloat162float(__high2bfloat16(hb2));
        hw[p] = *(uint32_t*)&hb2;
        __nv_bfloat162 lb2 = __floats2bfloat162_rn(a - ha, b - hbv);
        lw[p] = *(uint32_t*)&lb2;
    }
    *(uint4*)dhi = make_uint4(hw[0], hw[1], hw[2], hw[3]);
    *(uint4*)dlo = make_uint4(lw[0], lw[1], lw[2], lw[3]);
}
__device__ __forceinline__ void split_sts4(const float* xs, char* dhi, char* dlo) {
    uint32_t hw[2], lw[2];
    #pragma unroll
    for (int p = 0; p < 2; p++) {
        float a = xs[2 * p], b = xs[2 * p + 1];
        __nv_bfloat162 hb2 = __floats2bfloat162_rn(a, b);
        float ha = __bfloat162float(__low2bfloat16(hb2));
        float hbv = __bfloat162float(__high2bfloat16(hb2));
        hw[p] = *(uint32_t*)&hb2;
        __nv_bfloat162 lb2 = __floats2bfloat162_rn(a - ha, b - hbv);
        lw[p] = *(uint32_t*)&lb2;
    }
    *(uint2*)dhi = make_uint2(hw[0], hw[1]);
    *(uint2*)dlo = make_uint2(lw[0], lw[1]);
}
__device__ __forceinline__ void load8(float* d, const float* s) {
    float4 u = *(const float4*)s, v = *(const float4*)(s + 4);
    d[0] = u.x; d[1] = u.y; d[2] = u.z; d[3] = u.w;
    d[4] = v.x; d[5] = v.y; d[6] = v.z; d[7] = v.w;
}
__device__ __forceinline__ void load4(float* d, const float* s) {
    float4 u = *(const float4*)s;
    d[0] = u.x; d[1] = u.y; d[2] = u.z; d[3] = u.w;
}

// ===== smem layout =====
#define A_LD_B   48
#define A_PLANE  (128 * A_LD_B)        // 6144
#define B1_LD_B  272
#define B1_PLANE (16 * B1_LD_B)        // 4352
#define SMEM1_BYTES 24832              // k1
#define SMEM2_BYTES 24576              // k2: 4 planes of 6144

// ================= mm core 1: C[128,128] = A[bm:,512] @ W[512, bn:] (+bias) =================
__device__ __forceinline__ void mm_core1(const float* __restrict__ A,
                                         const float* __restrict__ W,
                                         float* __restrict__ C,
                                         const float* __restrict__ bias,
                                         int bm, int bn, char* smem) {
    const int tid = threadIdx.x, lane = tid & 31, wid = tid >> 5;
    const int wm = wid >> 2, wn = wid & 3;
    char* aHi = smem;                 char* aLo = smem + A_PLANE;
    char* bHi = smem + 2 * A_PLANE;   char* bLo = bHi + B1_PLANE;
    const uint32_t aHiU = smem_u32(aHi), aLoU = aHiU + A_PLANE;
    const uint32_t bHiU = aHiU + 2 * A_PLANE, bLoU = bHiU + B1_PLANE;

    const int arow = tid >> 1, ah = (tid & 1) * 8;
    const int bk = tid >> 4, bn8 = (tid & 15) * 8;
    const float* aSrc = A + (size_t)(bm + arow) * 512 + ah;
    const float* bSrc = W + (size_t)bk * 512 + bn + bn8;

    float acc[4][4][4];
    #pragma unroll
    for (int mt = 0; mt < 4; mt++)
        #pragma unroll
        for (int nt = 0; nt < 4; nt++)
            #pragma unroll
            for (int cc = 0; cc < 4; cc++) acc[mt][nt][cc] = 0.f;

    float pa[8], pb[8];
    load8(pa, aSrc);
    load8(pb, bSrc);

    for (int kt = 0; kt < 32; kt++) {
        split_sts8(pa, aHi + arow * A_LD_B + ah * 2, aLo + arow * A_LD_B + ah * 2);
        split_sts8(pb, bHi + bk * B1_LD_B + bn8 * 2, bLo + bk * B1_LD_B + bn8 * 2);
        __syncthreads();
        if (kt < 31) {
            load8(pa, aSrc + (kt + 1) * 16);
            load8(pb, bSrc + (size_t)(kt + 1) * 16 * 512);
        }
        uint32_t bfh[4][2], bfl[4][2];
        #pragma unroll
        for (int nt = 0; nt < 4; nt++) {
            uint32_t off = (lane & 15) * B1_LD_B + (wn * 32 + nt * 8) * 2;
            ldsm_x2_t(bfh[nt], bHiU + off);
            ldsm_x2_t(bfl[nt], bLoU + off);
        }
        #pragma unroll
        for (int mt = 0; mt < 4; mt++) {
            uint32_t aoff = (wm * 64 + mt * 16 + (lane & 15)) * A_LD_B + (lane >> 4) * 16;
            uint32_t fh[4], fl[4];
            ldsm_x4(fh, aHiU + aoff);
            ldsm_x4(fl, aLoU + aoff);
            #pragma unroll
            for (int nt = 0; nt < 4; nt++) {
                mma16816(acc[mt][nt], fh, bfh[nt]);
                mma16816(acc[mt][nt], fh, bfl[nt]);
                mma16816(acc[mt][nt], fl, bfh[nt]);
            }
        }
        __syncthreads();
    }

    #pragma unroll
    for (int mt = 0; mt < 4; mt++) {
        #pragma unroll
        for (int nt = 0; nt < 4; nt++) {
            int row = bm + wm * 64 + mt * 16 + (lane >> 2);
            int col = bn + wn * 32 + nt * 8 + 2 * (lane & 3);
            float b0 = bias ? bias[col] : 0.f;
            float b1 = bias ? bias[col + 1] : 0.f;
            float* c0 = C + (size_t)row * 512 + col;
            c0[0] = acc[mt][nt][0] + b0;
            c0[1] = acc[mt][nt][1] + b1;
            float* c1 = C + (size_t)(row + 8) * 512 + col;
            c1[0] = acc[mt][nt][2] + b0;
            c1[1] = acc[mt][nt][3] + b1;
        }
    }
}

// ================= mm core 2: einsum 128x128 tile, K-half, 512 threads =================
// part[t][s] = sum_{d in half} (P[t,n,d]+embproj[tg0,d]+qproj[tg1,n,d]) * srcE[s,n,d]
__device__ __forceinline__ void mm_core2(const int* __restrict__ tgt,
                                         const float* __restrict__ srcE,
                                         float* __restrict__ part,   // [n][t][s] base for this n
                                         int n, int kbase, char* smem) {
    const int tid = threadIdx.x, lane = tid & 31, wid = tid >> 5;
    const int wm = wid >> 2, wn = wid & 3;           // both 0..3
    char* aHi = smem;                 char* aLo = smem + A_PLANE;
    char* bHi = smem + 2 * A_PLANE;   char* bLo = bHi + A_PLANE;
    const uint32_t aHiU = smem_u32(aHi), aLoU = aHiU + A_PLANE;
    const uint32_t bHiU = aHiU + 2 * A_PLANE, bLoU = bHiU + A_PLANE;

    const int srow = tid >> 2;            // 0..127
    const int sk   = (tid & 3) * 4;       // 0,4,8,12

    const int tp = (srow + 1) & (TT - 1);
    const int* tg = tgt + ((size_t)tp * NN + n) * 3;
    const float* pA = g_P + ((size_t)srow * NN + n) * 512 + kbase + sk;
    const float* pE = g_embproj + (size_t)tg[0] * 512 + kbase + sk;
    const float* pQ = g_qproj + ((size_t)tg[1] * NN + n) * 512 + kbase + sk;
    const float* pB = srcE + ((size_t)srow * NN + n) * 512 + kbase + sk;

    float acc[2][4][4];
    #pragma unroll
    for (int mt = 0; mt < 2; mt++)
        #pragma unroll
        for (int nt = 0; nt < 4; nt++)
            #pragma unroll
            for (int cc = 0; cc < 4; cc++) acc[mt][nt][cc] = 0.f;

    float pa[4], pb[4];
    {
        float xa[4], xe[4], xq[4];
        load4(xa, pA); load4(xe, pE); load4(xq, pQ);
        #pragma unroll
        for (int i = 0; i < 4; i++) pa[i] = (xa[i] + xe[i]) + xq[i];
        load4(pb, pB);
    }

    for (int kt = 0; kt < 16; kt++) {
        split_sts4(pa, aHi + srow * A_LD_B + sk * 2, aLo + srow * A_LD_B + sk * 2);
        split_sts4(pb, bHi + srow * A_LD_B + sk * 2, bLo + srow * A_LD_B + sk * 2);
        __syncthreads();
        if (kt < 15) {
            int k0 = (kt + 1) * 16;
            float xa[4], xe[4], xq[4];
            load4(xa, pA + k0); load4(xe, pE + k0); load4(xq, pQ + k0);
            #pragma unroll
            for (int i = 0; i < 4; i++) pa[i] = (xa[i] + xe[i]) + xq[i];
            load4(pb, pB + k0);
        }
        uint32_t bfh[4][2], bfl[4][2];
        #pragma unroll
        for (int nt = 0; nt < 4; nt++) {
            uint32_t off = (wn * 32 + nt * 8 + (lane & 7)) * A_LD_B + ((lane >> 3) & 1) * 16;
            ldsm_x2(bfh[nt], bHiU + off);
            ldsm_x2(bfl[nt], bLoU + off);
        }
        #pragma unroll
        for (int mt = 0; mt < 2; mt++) {
            uint32_t aoff = (wm * 32 + mt * 16 + (lane & 15)) * A_LD_B + (lane >> 4) * 16;
            uint32_t fh[4], fl[4];
            ldsm_x4(fh, aHiU + aoff);
            ldsm_x4(fl, aLoU + aoff);
            #pragma unroll
            for (int nt = 0; nt < 4; nt++) {
                mma16816(acc[mt][nt], fh, bfh[nt]);
                mma16816(acc[mt][nt], fh, bfl[nt]);
                mma16816(acc[mt][nt], fl, bfh[nt]);
            }
        }
        __syncthreads();
    }

    // coalesced partial store: part[t*128 + s]
    #pragma unroll
    for (int mt = 0; mt < 2; mt++) {
        #pragma unroll
        for (int nt = 0; nt < 4; nt++) {
            int t = wm * 32 + mt * 16 + (lane >> 2);
            int s = wn * 32 + nt * 8 + 2 * (lane & 3);
            float* p0 = part + (size_t)t * 128 + s;
            p0[0] = acc[mt][nt][0];
            p0[1] = acc[mt][nt][1];
            float* p1 = part + (size_t)(t + 8) * 128 + s;
            p1[0] = acc[mt][nt][2];
            p1[1] = acc[mt][nt][3];
        }
    }
}

// ================= k1: 466 blocks x 256 threads =================
__global__ __launch_bounds__(256, 2) void k1(const float* __restrict__ dec,
                                             const float* __restrict__ srcE,
                                             const float* __restrict__ emb,
                                             const float* __restrict__ Wo,
                                             const float* __restrict__ bo,
                                             const float* __restrict__ Wd) {
    __shared__ __align__(16) char smem[SMEM1_BYTES];
    const int bid = blockIdx.x, tid = threadIdx.x;

    if (bid < 256) {
        mm_core1(dec, Wo, g_P, bo, (bid >> 2) * 128, (bid & 3) * 128, smem);
    } else if (bid < 268) {
        int q = bid - 256;
        mm_core1(srcE, Wo + (size_t)2 * D * D, g_qproj, (const float*)0,
                 (q >> 2) * 128, (q & 3) * 128, smem);
    } else if (bid < 274) {
        int i = bid - 268;
        float* e = (float*)smem;
        e[tid]       = emb[i * D + tid];
        e[tid + 256] = emb[i * D + tid + 256];
        __syncthreads();
        #pragma unroll
        for (int half = 0; half < 2; half++) {
            int c = tid + half * 256;
            float acc = 0.f;
            const float* wb = Wo + (size_t)D * D + c;
            #pragma unroll 8
            for (int k = 0; k < D; k++) acc += e[k] * wb[(size_t)k * D];
            g_embproj[i * D + c] = acc;
        }
        if (tid < 5) {
            float a = 0.f;
            const float* wd = Wd + (size_t)D * 5 + tid;
            for (int k = 0; k < D; k++) a += e[k] * wd[k * 5];
            g_embdir[i * 5 + tid] = a;
        }
    } else {
        const int g  = tid >> 7;
        const int lt = tid & 127;
        const int r  = (bid - 274) * 2 + g;
        float acc[10];
        #pragma unroll
        for (int j = 0; j < 10; j++) acc[j] = 0.f;
        const float* row = srcE + (size_t)r * D;
        for (int k = lt; k < D; k += 128) {
            float v = row[k];
            const float* w2 = Wd + (size_t)(2 * D + k) * 5;
            const float* w3 = Wd + (size_t)(3 * D + k) * 5;
            #pragma unroll
            for (int j = 0; j < 5; j++) {
                acc[j]     += v * w2[j];
                acc[5 + j] += v * w3[j];
            }
        }
        #pragma unroll
        for (int off = 16; off; off >>= 1)
            #pragma unroll
            for (int j = 0; j < 10; j++)
                acc[j] += __shfl_down_sync(0xffffffffu, acc[j], off);
        float* red = (float*)smem;
        const int w = tid >> 5, lane = tid & 31;
        if (lane == 0)
            #pragma unroll
            for (int j = 0; j < 10; j++) red[w * 10 + j] = acc[j];
        __syncthreads();
        if (lt < 10) {
            int wb = g * 4;
            float s = red[(wb + 0) * 10 + lt] + red[(wb + 1) * 10 + lt]
                    + red[(wb + 2) * 10 + lt] + red[(wb + 3) * 10 + lt];
            if (lt < 5) g_qdir[r * 5 + lt] = s;
            else        g_rdir[r * 5 + (lt - 5)] = s;
        }
    }
}

// ================= k2: 168 blocks x 512 threads =================
//  [0,128)   einsum partial (n = bid>>1, K-half = bid&1)
//  [128,168) typedir (205 rows each)
__global__ __launch_bounds__(512, 1) void k2(const float* __restrict__ srcE,
                                             const int* __restrict__ tgt,
                                             const float* __restrict__ dec,
                                             const float* __restrict__ Wt,
                                             const float* __restrict__ bt,
                                             const float* __restrict__ Wd,
                                             const float* __restrict__ bd,
                                             float* __restrict__ out_type,
                                             float* __restrict__ out_dir) {
    __shared__ __align__(16) char smem[SMEM2_BYTES];
    const int bid = blockIdx.x, tid = threadIdx.x;

    if (bid < 128) {
        const int n = bid >> 1, half = bid & 1;
        mm_core2(tgt, srcE, &g_part[half][(size_t)n * 128 * 128], n, half * 256, smem);
    } else {
        float* sW = (float*)smem;                          // 512 x 11
        for (int i = tid; i < D * 6; i += 512) {
            int k = i / 6, c = i % 6;
            sW[k * 11 + c] = Wt[i];
        }
        for (int i = tid; i < D * 5; i += 512) {
            int k = i / 5, c = i % 5;
            sW[k * 11 + 6 + c] = Wd[i];
        }
        __syncthreads();
        const int w = tid >> 5, lane = tid & 31;
        const int r0 = (bid - 128) * 205;
        int rend = r0 + 205;
        if (rend > 8192) rend = 8192;
        for (int r = r0 + w; r < rend; r += 16) {
            const float* drow = dec + (size_t)r * D;
            float acc[11];
            #pragma unroll
            for (int c = 0; c < 11; c++) acc[c] = 0.f;
            #pragma unroll 4
            for (int u = 0; u < 16; u++) {
                int k = u * 32 + lane;
                float v = drow[k];
                const float* wp = &sW[k * 11];
                #pragma unroll
                for (int c = 0; c < 11; c++) acc[c] += v * wp[c];
            }
            #pragma unroll
            for (int off = 16; off; off >>= 1)
                #pragma unroll
                for (int c = 0; c < 11; c++)
                    acc[c] += __shfl_xor_sync(0xffffffffu, acc[c], off);
            if (lane < 11) {
                int t = r >> 6, n = r & 63;
                int tp = (t + 1) & (TT - 1);
                const int* tg = tgt + ((size_t)tp * NN + n) * 3;
                if (lane < 6) {
                    out_type[(size_t)r * 6 + lane] = acc[lane] + bt[lane];
                } else {
                    int j = lane - 6;
                    out_dir[(size_t)r * 5 + j] = acc[lane] + bd[j]
                        + g_embdir[tg[0] * 5 + j]
                        + g_qdir[((size_t)tg[1] * NN + n) * 5 + j]
                        + g_rdir[((size_t)tg[2] * NN + n) * 5 + j];
                }
            }
        }
    }
}

// ================= k3: combine partials + mask -> out_obj =================
// 128 blocks x 256 threads: n = bid>>1, t-half = bid&1 (64 t rows x 128 s)
__global__ __launch_bounds__(256) void k3(const unsigned char* __restrict__ mask,
                                          float* __restrict__ out_obj) {
    const int bid = blockIdx.x, tid = threadIdx.x;
    const int n = bid >> 1;
    const int t0 = (bid & 1) * 64;
    const float NEG_INF = __int_as_float(0xff800000);

    const float* p0 = &g_part[0][(size_t)n * 128 * 128];
    const float* p1 = &g_part[1][(size_t)n * 128 * 128];

    for (int idx = tid; idx < 64 * 32; idx += 256) {
        int tt = t0 + (idx >> 5);
        int s4 = (idx & 31) * 4;
        float4 a = *(const float4*)(p0 + (size_t)tt * 128 + s4);
        float4 b = *(const float4*)(p1 + (size_t)tt * 128 + s4);
        uchar4 m = *(const uchar4*)(mask + n * SS + s4);
        float4 r;
        r.x = m.x ? NEG_INF : a.x + b.x;
        r.y = m.y ? NEG_INF : a.y + b.y;
        r.z = m.z ? NEG_INF : a.z + b.z;
        r.w = m.w ? NEG_INF : a.w + b.w;
        *(float4*)(out_obj + ((size_t)tt * NN + n) * SS + s4) = r;
    }
}

// ================= launch =================
extern "C" void kernel_launch(void* const* d_in, const int* in_sizes, int n_in,
                              void* d_out, int out_size) {
    const float*         dec  = (const float*)d_in[0];   // (T,N,D)
    const int*           tgt  = (const int*)d_in[1];     // (T,N,3)
    const float*         srcE = (const float*)d_in[2];   // (S,N,D)
    const unsigned char* mask = (const unsigned char*)d_in[3]; // (N,S) bool
    const float*         emb  = (const float*)d_in[4];   // (6,D)
    const float*         Wt   = (const float*)d_in[5];   // (D,6)
    const float*         bt   = (const float*)d_in[6];   // (6,)
    const float*         Wo   = (const float*)d_in[7];   // (3D,D)
    const float*         bo   = (const float*)d_in[8];   // (D,)
    const float*         Wd   = (const float*)d_in[9];   // (4D,5)
    const float*         bd   = (const float*)d_in[10];  // (5,)

    float* out      = (float*)d_out;
    float* out_type = out;                                    // (T,N,6)
    float* out_obj  = out + (size_t)TT * NN * 6;              // (T,N,S)
    float* out_dir  = out + (size_t)TT * NN * 6 + (size_t)TT * NN * SS; // (T,N,5)

    k1<<<466, 256>>>(dec, srcE, emb, Wo, bo, Wd);
    k2<<<168, 512>>>(srcE, tgt, dec, Wt, bt, Wd, bd, out_type, out_dir);
    k3<<<128, 256>>>(mask, out_obj);
}

// round 13
// speedup vs baseline: 1.3529x; 1.3529x over previous
#include <cuda_runtime.h>
#include <cuda_bf16.h>
#include <cstdint>

#define D  512
#define TT 128
#define NN 64
#define SS 128

// ---- scratch (static device globals; no allocation) ----
__device__ float g_P[8192 * 512];        // dec @ W0 + b_obj
__device__ float g_qproj[384 * 512];     // src_e[0:6] @ W_obj[1024:1536]
__device__ float g_embproj[6 * 512];
__device__ float g_embdir[6 * 5];
__device__ float g_qdir[384 * 5];
__device__ float g_rdir[384 * 5];
__device__ __align__(16) __nv_bfloat16 g_W0h[512 * 512], g_W0l[512 * 512];  // split W_obj[0:512]
__device__ __align__(16) __nv_bfloat16 g_W2h[512 * 512], g_W2l[512 * 512];  // split W_obj[1024:1536]

// ================= warp-level tensor helpers (sm_80+ base-target) =================
__device__ __forceinline__ uint32_t smem_u32(const void* p) {
    uint32_t a;
    asm("{ .reg .u64 t; cvta.to.shared.u64 t, %1; cvt.u32.u64 %0, t; }" : "=r"(a) : "l"(p));
    return a;
}
__device__ __forceinline__ void ldsm_x4(uint32_t* r, uint32_t addr) {
    asm volatile("ldmatrix.sync.aligned.m8n8.x4.shared.b16 {%0,%1,%2,%3}, [%4];"
                 : "=r"(r[0]), "=r"(r[1]), "=r"(r[2]), "=r"(r[3]) : "r"(addr));
}
__device__ __forceinline__ void ldsm_x2(uint32_t* r, uint32_t addr) {
    asm volatile("ldmatrix.sync.aligned.m8n8.x2.shared.b16 {%0,%1}, [%2];"
                 : "=r"(r[0]), "=r"(r[1]) : "r"(addr));
}
__device__ __forceinline__ void ldsm_x2_t(uint32_t* r, uint32_t addr) {
    asm volatile("ldmatrix.sync.aligned.m8n8.x2.trans.shared.b16 {%0,%1}, [%2];"
                 : "=r"(r[0]), "=r"(r[1]) : "r"(addr));
}
__device__ __forceinline__ void mma16816(float* c, const uint32_t* a, const uint32_t* b) {
    asm volatile("mma.sync.aligned.m16n8k16.row.col.f32.bf16.bf16.f32 "
                 "{%0,%1,%2,%3}, {%4,%5,%6,%7}, {%8,%9}, {%0,%1,%2,%3};"
                 : "+f"(c[0]), "+f"(c[1]), "+f"(c[2]), "+f"(c[3])
                 : "r"(a[0]), "r"(a[1]), "r"(a[2]), "r"(a[3]), "r"(b[0]), "r"(b[1]));
}

// ---- fp32 -> bf16 hi/lo split helpers ----
__device__ __forceinline__ void split_sts8(const float* xs, char* dhi, char* dlo) {
    uint32_t hw[4], lw[4];
    #pragma unroll
    for (int p = 0; p < 4; p++) {
        float a = xs[2 * p], b = xs[2 * p + 1];
        __nv_bfloat162 hb2 = __floats2bfloat162_rn(a, b);
        float ha = __bfloat162float(__low2bfloat16(hb2));
        float hbv = __bfloat162float(__high2bfloat16(hb2));
        hw[p] = *(uint32_t*)&hb2;
        __nv_bfloat162 lb2 = __floats2bfloat162_rn(a - ha, b - hbv);
        lw[p] = *(uint32_t*)&lb2;
    }
    *(uint4*)dhi = make_uint4(hw[0], hw[1], hw[2], hw[3]);
    *(uint4*)dlo = make_uint4(lw[0], lw[1], lw[2], lw[3]);
}
__device__ __forceinline__ void split_sts4(const float* xs, char* dhi, char* dlo) {
    uint32_t hw[2], lw[2];
    #pragma unroll
    for (int p = 0; p < 2; p++) {
        float a = xs[2 * p], b = xs[2 * p + 1];
        __nv_bfloat162 hb2 = __floats2bfloat162_rn(a, b);
        float ha = __bfloat162float(__low2bfloat16(hb2));
        float hbv = __bfloat162float(__high2bfloat16(hb2));
        hw[p] = *(uint32_t*)&hb2;
        __nv_bfloat162 lb2 = __floats2bfloat162_rn(a - ha, b - hbv);
        lw[p] = *(uint32_t*)&lb2;
    }
    *(uint2*)dhi = make_uint2(hw[0], hw[1]);
    *(uint2*)dlo = make_uint2(lw[0], lw[1]);
}
__device__ __forceinline__ void load8(float* d, const float* s) {
    float4 u = *(const float4*)s, v = *(const float4*)(s + 4);
    d[0] = u.x; d[1] = u.y; d[2] = u.z; d[3] = u.w;
    d[4] = v.x; d[5] = v.y; d[6] = v.z; d[7] = v.w;
}
__device__ __forceinline__ void load4(float* d, const float* s) {
    float4 u = *(const float4*)s;
    d[0] = u.x; d[1] = u.y; d[2] = u.z; d[3] = u.w;
}

// ===== smem layout =====
#define A_LD_B    48
#define A_PLANE   (128 * A_LD_B)       // 6144
#define B1_LD_B   272
#define B1_PLANE  (16 * B1_LD_B)       // 4352
#define BUF1_B    (2 * A_PLANE + 2 * B1_PLANE)  // 20992 per buffer
#define SMEM1_BYTES (2 * BUF1_B)       // 41984 (k1, double-buffered)
#define SMEM2_BYTES 24576              // k2: 4 planes of 6144

// ================= k0: pre-split W0 / W2 to bf16 hi/lo =================
// 128 blocks x 256 threads; bid<64 -> W0, else W2; 4096 elems per block.
__global__ __launch_bounds__(256) void k0(const float* __restrict__ Wo) {
    const int bid = blockIdx.x, tid = threadIdx.x;
    const float* src = (bid < 64) ? Wo : (Wo + (size_t)2 * D * D);
    __nv_bfloat16* dh = (bid < 64) ? g_W0h : g_W2h;
    __nv_bfloat16* dl = (bid < 64) ? g_W0l : g_W2l;
    const size_t base = (size_t)(bid & 63) * 4096;
    #pragma unroll
    for (int i = 0; i < 2; i++) {
        size_t off = base + (size_t)(tid + i * 256) * 8;
        float xs[8];
        load8(xs, src + off);
        split_sts8(xs, (char*)(dh + off), (char*)(dl + off));
    }
}

// ================= mm core 1: C[128,128] = A[bm:,512] @ W[512, bn:] (+bias) =================
// A fp32 (split at stage time); W pre-split bf16 hi/lo (K-major). Double-buffered.
__device__ __forceinline__ void mm_core1(const float* __restrict__ A,
                                         const __nv_bfloat16* __restrict__ Wh,
                                         const __nv_bfloat16* __restrict__ Wl,
                                         float* __restrict__ C,
                                         const float* __restrict__ bias,
                                         int bm, int bn, char* smem) {
    const int tid = threadIdx.x, lane = tid & 31, wid = tid >> 5;
    const int wm = wid >> 2, wn = wid & 3;
    const uint32_t sU = smem_u32(smem);

    const int arow = tid >> 1, ah = (tid & 1) * 8;
    const int bk = tid >> 4, bn8 = (tid & 15) * 8;
    const float* aSrc = A + (size_t)(bm + arow) * 512 + ah;
    const __nv_bfloat16* bhSrc = Wh + (size_t)bk * 512 + bn + bn8;
    const __nv_bfloat16* blSrc = Wl + (size_t)bk * 512 + bn + bn8;

    float acc[4][4][4];
    #pragma unroll
    for (int mt = 0; mt < 4; mt++)
        #pragma unroll
        for (int nt = 0; nt < 4; nt++)
            #pragma unroll
            for (int cc = 0; cc < 4; cc++) acc[mt][nt][cc] = 0.f;

    float pa[8];
    uint4 pbh, pbl;
    load8(pa, aSrc);
    pbh = *(const uint4*)bhSrc;
    pbl = *(const uint4*)blSrc;
    {
        char* b0 = smem;
        split_sts8(pa, b0 + arow * A_LD_B + ah * 2, b0 + A_PLANE + arow * A_LD_B + ah * 2);
        *(uint4*)(b0 + 2 * A_PLANE + bk * B1_LD_B + bn8 * 2) = pbh;
        *(uint4*)(b0 + 2 * A_PLANE + B1_PLANE + bk * B1_LD_B + bn8 * 2) = pbl;
    }
    __syncthreads();

    for (int kt = 0; kt < 32; kt++) {
        const int cb = kt & 1;
        const bool more = (kt < 31);
        if (more) {
            load8(pa, aSrc + (kt + 1) * 16);
            pbh = *(const uint4*)(bhSrc + (size_t)(kt + 1) * 16 * 512);
            pbl = *(const uint4*)(blSrc + (size_t)(kt + 1) * 16 * 512);
        }
        const uint32_t base = sU + cb * BUF1_B;
        const uint32_t aHiU = base, aLoU = base + A_PLANE;
        const uint32_t bHiU = base + 2 * A_PLANE, bLoU = bHiU + B1_PLANE;
        uint32_t bfh[4][2], bfl[4][2];
        #pragma unroll
        for (int nt = 0; nt < 4; nt++) {
            uint32_t off = (lane & 15) * B1_LD_B + (wn * 32 + nt * 8) * 2;
            ldsm_x2_t(bfh[nt], bHiU + off);
            ldsm_x2_t(bfl[nt], bLoU + off);
        }
        #pragma unroll
        for (int mt = 0; mt < 4; mt++) {
            uint32_t aoff = (wm * 64 + mt * 16 + (lane & 15)) * A_LD_B + (lane >> 4) * 16;
            uint32_t fh[4], fl[4];
            ldsm_x4(fh, aHiU + aoff);
            ldsm_x4(fl, aLoU + aoff);
            #pragma unroll
            for (int nt = 0; nt < 4; nt++) {
                mma16816(acc[mt][nt], fh, bfh[nt]);
                mma16816(acc[mt][nt], fh, bfl[nt]);
                mma16816(acc[mt][nt], fl, bfh[nt]);
            }
        }
        if (more) {
            char* nb = smem + (cb ^ 1) * BUF1_B;
            split_sts8(pa, nb + arow * A_LD_B + ah * 2, nb + A_PLANE + arow * A_LD_B + ah * 2);
            *(uint4*)(nb + 2 * A_PLANE + bk * B1_LD_B + bn8 * 2) = pbh;
            *(uint4*)(nb + 2 * A_PLANE + B1_PLANE + bk * B1_LD_B + bn8 * 2) = pbl;
            __syncthreads();
        }
    }

    #pragma unroll
    for (int mt = 0; mt < 4; mt++) {
        #pragma unroll
        for (int nt = 0; nt < 4; nt++) {
            int row = bm + wm * 64 + mt * 16 + (lane >> 2);
            int col = bn + wn * 32 + nt * 8 + 2 * (lane & 3);
            float b0 = bias ? bias[col] : 0.f;
            float b1 = bias ? bias[col + 1] : 0.f;
            float* c0 = C + (size_t)row * 512 + col;
            c0[0] = acc[mt][nt][0] + b0;
            c0[1] = acc[mt][nt][1] + b1;
            float* c1 = C + (size_t)(row + 8) * 512 + col;
            c1[0] = acc[mt][nt][2] + b0;
            c1[1] = acc[mt][nt][3] + b1;
        }
    }
}

// ================= mm core 2: einsum 128x128 tile, 512 threads (R11 form) =================
__device__ __forceinline__ void mm_core2(const int* __restrict__ tgt,
                                         const float* __restrict__ srcE,
                                         const unsigned char* __restrict__ mask,
                                         float* __restrict__ out_obj,
                                         int n, char* smem) {
    const int tid = threadIdx.x, lane = tid & 31, wid = tid >> 5;
    const int wm = wid >> 2, wn = wid & 3;
    char* aHi = smem;                 char* aLo = smem + A_PLANE;
    char* bHi = smem + 2 * A_PLANE;   char* bLo = bHi + A_PLANE;
    const uint32_t aHiU = smem_u32(aHi), aLoU = aHiU + A_PLANE;
    const uint32_t bHiU = aHiU + 2 * A_PLANE, bLoU = bHiU + A_PLANE;

    const int srow = tid >> 2;
    const int sk   = (tid & 3) * 4;

    const int tp = (srow + 1) & (TT - 1);
    const int* tg = tgt + ((size_t)tp * NN + n) * 3;
    const float* pA = g_P + ((size_t)srow * NN + n) * 512 + sk;
    const float* pE = g_embproj + (size_t)tg[0] * 512 + sk;
    const float* pQ = g_qproj + ((size_t)tg[1] * NN + n) * 512 + sk;
    const float* pB = srcE + ((size_t)srow * NN + n) * 512 + sk;

    float acc[2][4][4];
    #pragma unroll
    for (int mt = 0; mt < 2; mt++)
        #pragma unroll
        for (int nt = 0; nt < 4; nt++)
            #pragma unroll
            for (int cc = 0; cc < 4; cc++) acc[mt][nt][cc] = 0.f;

    float pa[4], pb[4];
    {
        float xa[4], xe[4], xq[4];
        load4(xa, pA); load4(xe, pE); load4(xq, pQ);
        #pragma unroll
        for (int i = 0; i < 4; i++) pa[i] = (xa[i] + xe[i]) + xq[i];
        load4(pb, pB);
    }

    for (int kt = 0; kt < 32; kt++) {
        split_sts4(pa, aHi + srow * A_LD_B + sk * 2, aLo + srow * A_LD_B + sk * 2);
        split_sts4(pb, bHi + srow * A_LD_B + sk * 2, bLo + srow * A_LD_B + sk * 2);
        __syncthreads();
        if (kt < 31) {
            int k0 = (kt + 1) * 16;
            float xa[4], xe[4], xq[4];
            load4(xa, pA + k0); load4(xe, pE + k0); load4(xq, pQ + k0);
            #pragma unroll
            for (int i = 0; i < 4; i++) pa[i] = (xa[i] + xe[i]) + xq[i];
            load4(pb, pB + k0);
        }
        uint32_t bfh[4][2], bfl[4][2];
        #pragma unroll
        for (int nt = 0; nt < 4; nt++) {
            uint32_t off = (wn * 32 + nt * 8 + (lane & 7)) * A_LD_B + ((lane >> 3) & 1) * 16;
            ldsm_x2(bfh[nt], bHiU + off);
            ldsm_x2(bfl[nt], bLoU + off);
        }
        #pragma unroll
        for (int mt = 0; mt < 2; mt++) {
            uint32_t aoff = (wm * 32 + mt * 16 + (lane & 15)) * A_LD_B + (lane >> 4) * 16;
            uint32_t fh[4], fl[4];
            ldsm_x4(fh, aHiU + aoff);
            ldsm_x4(fl, aLoU + aoff);
            #pragma unroll
            for (int nt = 0; nt < 4; nt++) {
                mma16816(acc[mt][nt], fh, bfh[nt]);
                mma16816(acc[mt][nt], fh, bfl[nt]);
                mma16816(acc[mt][nt], fl, bfh[nt]);
            }
        }
        __syncthreads();
    }

    const float NEG_INF = __int_as_float(0xff800000);
    #pragma unroll
    for (int mt = 0; mt < 2; mt++) {
        #pragma unroll
        for (int nt = 0; nt < 4; nt++) {
            int t = wm * 32 + mt * 16 + (lane >> 2);
            int s = wn * 32 + nt * 8 + 2 * (lane & 3);
            unsigned char m0 = mask[n * SS + s], m1 = mask[n * SS + s + 1];
            float* o0 = out_obj + ((size_t)t * NN + n) * SS + s;
            o0[0] = m0 ? NEG_INF : acc[mt][nt][0];
            o0[1] = m1 ? NEG_INF : acc[mt][nt][1];
            float* o1 = out_obj + ((size_t)(t + 8) * NN + n) * SS + s;
            o1[0] = m0 ? NEG_INF : acc[mt][nt][2];
            o1[1] = m1 ? NEG_INF : acc[mt][nt][3];
        }
    }
}

// ================= k1: 466 blocks x 256 threads =================
__global__ __launch_bounds__(256, 2) void k1(const float* __restrict__ dec,
                                             const float* __restrict__ srcE,
                                             const float* __restrict__ emb,
                                             const float* __restrict__ Wo,
                                             const float* __restrict__ bo,
                                             const float* __restrict__ Wd) {
    __shared__ __align__(16) char smem[SMEM1_BYTES];
    const int bid = blockIdx.x, tid = threadIdx.x;

    if (bid < 256) {
        mm_core1(dec, g_W0h, g_W0l, g_P, bo, (bid >> 2) * 128, (bid & 3) * 128, smem);
    } else if (bid < 268) {
        int q = bid - 256;
        mm_core1(srcE, g_W2h, g_W2l, g_qproj, (const float*)0,
                 (q >> 2) * 128, (q & 3) * 128, smem);
    } else if (bid < 274) {
        int i = bid - 268;
        float* e = (float*)smem;
        e[tid]       = emb[i * D + tid];
        e[tid + 256] = emb[i * D + tid + 256];
        __syncthreads();
        #pragma unroll
        for (int half = 0; half < 2; half++) {
            int c = tid + half * 256;
            float acc = 0.f;
            const float* wb = Wo + (size_t)D * D + c;
            #pragma unroll 8
            for (int k = 0; k < D; k++) acc += e[k] * wb[(size_t)k * D];
            g_embproj[i * D + c] = acc;
        }
        if (tid < 5) {
            float a = 0.f;
            const float* wd = Wd + (size_t)D * 5 + tid;
            for (int k = 0; k < D; k++) a += e[k] * wd[k * 5];
            g_embdir[i * 5 + tid] = a;
        }
    } else {
        const int g  = tid >> 7;
        const int lt = tid & 127;
        const int r  = (bid - 274) * 2 + g;
        float acc[10];
        #pragma unroll
        for (int j = 0; j < 10; j++) acc[j] = 0.f;
        const float* row = srcE + (size_t)r * D;
        for (int k = lt; k < D; k += 128) {
            float v = row[k];
            const float* w2 = Wd + (size_t)(2 * D + k) * 5;
            const float* w3 = Wd + (size_t)(3 * D + k) * 5;
            #pragma unroll
            for (int j = 0; j < 5; j++) {
                acc[j]     += v * w2[j];
                acc[5 + j] += v * w3[j];
            }
        }
        #pragma unroll
        for (int off = 16; off; off >>= 1)
            #pragma unroll
            for (int j = 0; j < 10; j++)
                acc[j] += __shfl_down_sync(0xffffffffu, acc[j], off);
        float* red = (float*)smem;
        const int w = tid >> 5, lane = tid & 31;
        if (lane == 0)
            #pragma unroll
            for (int j = 0; j < 10; j++) red[w * 10 + j] = acc[j];
        __syncthreads();
        if (lt < 10) {
            int wb = g * 4;
            float s = red[(wb + 0) * 10 + lt] + red[(wb + 1) * 10 + lt]
                    + red[(wb + 2) * 10 + lt] + red[(wb + 3) * 10 + lt];
            if (lt < 5) g_qdir[r * 5 + lt] = s;
            else        g_rdir[r * 5 + (lt - 5)] = s;
        }
    }
}

// ================= k2: 104 blocks x 512 threads (R11 form) =================
__global__ __launch_bounds__(512, 1) void k2(const float* __restrict__ srcE,
                                             const unsigned char* __restrict__ mask,
                                             const int* __restrict__ tgt,
                                             const float* __restrict__ dec,
                                             const float* __restrict__ Wt,
                                             const float* __restrict__ bt,
                                             const float* __restrict__ Wd,
                                             const float* __restrict__ bd,
                                             float* __restrict__ out_type,
                                             float* __restrict__ out_obj,
                                             float* __restrict__ out_dir) {
    __shared__ __align__(16) char smem[SMEM2_BYTES];
    const int bid = blockIdx.x, tid = threadIdx.x;

    if (bid < 64) {
        mm_core2(tgt, srcE, mask, out_obj, bid, smem);
    } else {
        float* sW = (float*)smem;                          // 512 x 11
        for (int i = tid; i < D * 6; i += 512) {
            int k = i / 6, c = i % 6;
            sW[k * 11 + c] = Wt[i];
        }
        for (int i = tid; i < D * 5; i += 512) {
            int k = i / 5, c = i % 5;
            sW[k * 11 + 6 + c] = Wd[i];
        }
        __syncthreads();
        const int w = tid >> 5, lane = tid & 31;
        const int r0 = (bid - 64) * 205;
        int rend = r0 + 205;
        if (rend > 8192) rend = 8192;
        for (int r = r0 + w; r < rend; r += 16) {
            const float* drow = dec + (size_t)r * D;
            float acc[11];
            #pragma unroll
            for (int c = 0; c < 11; c++) acc[c] = 0.f;
            #pragma unroll 4
            for (int u = 0; u < 16; u++) {
                int k = u * 32 + lane;
                float v = drow[k];
                const float* wp = &sW[k * 11];
                #pragma unroll
                for (int c = 0; c < 11; c++) acc[c] += v * wp[c];
            }
            #pragma unroll
            for (int off = 16; off; off >>= 1)
                #pragma unroll
                for (int c = 0; c < 11; c++)
                    acc[c] += __shfl_xor_sync(0xffffffffu, acc[c], off);
            if (lane < 11) {
                int t = r >> 6, n = r & 63;
                int tp = (t + 1) & (TT - 1);
                const int* tg = tgt + ((size_t)tp * NN + n) * 3;
                if (lane < 6) {
                    out_type[(size_t)r * 6 + lane] = acc[lane] + bt[lane];
                } else {
                    int j = lane - 6;
                    out_dir[(size_t)r * 5 + j] = acc[lane] + bd[j]
                        + g_embdir[tg[0] * 5 + j]
                        + g_qdir[((size_t)tg[1] * NN + n) * 5 + j]
                        + g_rdir[((size_t)tg[2] * NN + n) * 5 + j];
                }
            }
        }
    }
}

// ================= launch =================
extern "C" void kernel_launch(void* const* d_in, const int* in_sizes, int n_in,
                              void* d_out, int out_size) {
    const float*         dec  = (const float*)d_in[0];   // (T,N,D)
    const int*           tgt  = (const int*)d_in[1];     // (T,N,3)
    const float*         srcE = (const float*)d_in[2];   // (S,N,D)
    const unsigned char* mask = (const unsigned char*)d_in[3]; // (N,S) bool
    const float*         emb  = (const float*)d_in[4];   // (6,D)
    const float*         Wt   = (const float*)d_in[5];   // (D,6)
    const float*         bt   = (const float*)d_in[6];   // (6,)
    const float*         Wo   = (const float*)d_in[7];   // (3D,D)
    const float*         bo   = (const float*)d_in[8];   // (D,)
    const float*         Wd   = (const float*)d_in[9];   // (4D,5)
    const float*         bd   = (const float*)d_in[10];  // (5,)

    float* out      = (float*)d_out;
    float* out_type = out;                                    // (T,N,6)
    float* out_obj  = out + (size_t)TT * NN * 6;              // (T,N,S)
    float* out_dir  = out + (size_t)TT * NN * 6 + (size_t)TT * NN * SS; // (T,N,5)

    k0<<<128, 256>>>(Wo);
    k1<<<466, 256>>>(dec, srcE, emb, Wo, bo, Wd);
    k2<<<104, 512>>>(srcE, mask, tgt, dec, Wt, bt, Wd, bd,
                     out_type, out_obj, out_dir);
}

// round 14
// speedup vs baseline: 1.3886x; 1.0264x over previous
#include <cuda_runtime.h>
#include <cuda_bf16.h>
#include <cstdint>

#define D  512
#define TT 128
#define NN 64
#define SS 128

// ---- scratch (static device globals; no allocation) ----
__device__ float g_P[8192 * 512];        // dec @ W0 + b_obj
__device__ float g_qproj[384 * 512];     // src_e[0:6] @ W_obj[1024:1536]
__device__ float g_embproj[6 * 512];
__device__ float g_embdir[6 * 5];
__device__ float g_qdir[384 * 5];
__device__ float g_rdir[384 * 5];
__device__ __align__(16) __nv_bfloat16 g_W0h[512 * 512], g_W0l[512 * 512];  // split W_obj[0:512]
__device__ __align__(16) __nv_bfloat16 g_W2h[512 * 512], g_W2l[512 * 512];  // split W_obj[1024:1536]

// ================= warp-level tensor helpers (sm_80+ base-target) =================
__device__ __forceinline__ uint32_t smem_u32(const void* p) {
    uint32_t a;
    asm("{ .reg .u64 t; cvta.to.shared.u64 t, %1; cvt.u32.u64 %0, t; }" : "=r"(a) : "l"(p));
    return a;
}
__device__ __forceinline__ void ldsm_x4(uint32_t* r, uint32_t addr) {
    asm volatile("ldmatrix.sync.aligned.m8n8.x4.shared.b16 {%0,%1,%2,%3}, [%4];"
                 : "=r"(r[0]), "=r"(r[1]), "=r"(r[2]), "=r"(r[3]) : "r"(addr));
}
__device__ __forceinline__ void ldsm_x2(uint32_t* r, uint32_t addr) {
    asm volatile("ldmatrix.sync.aligned.m8n8.x2.shared.b16 {%0,%1}, [%2];"
                 : "=r"(r[0]), "=r"(r[1]) : "r"(addr));
}
__device__ __forceinline__ void ldsm_x2_t(uint32_t* r, uint32_t addr) {
    asm volatile("ldmatrix.sync.aligned.m8n8.x2.trans.shared.b16 {%0,%1}, [%2];"
                 : "=r"(r[0]), "=r"(r[1]) : "r"(addr));
}
__device__ __forceinline__ void mma16816(float* c, const uint32_t* a, const uint32_t* b) {
    asm volatile("mma.sync.aligned.m16n8k16.row.col.f32.bf16.bf16.f32 "
                 "{%0,%1,%2,%3}, {%4,%5,%6,%7}, {%8,%9}, {%0,%1,%2,%3};"
                 : "+f"(c[0]), "+f"(c[1]), "+f"(c[2]), "+f"(c[3])
                 : "r"(a[0]), "r"(a[1]), "r"(a[2]), "r"(a[3]), "r"(b[0]), "r"(b[1]));
}

// ---- fp32 -> bf16 hi/lo split helpers ----
__device__ __forceinline__ void split_sts8(const float* xs, char* dhi, char* dlo) {
    uint32_t hw[4], lw[4];
    #pragma unroll
    for (int p = 0; p < 4; p++) {
        float a = xs[2 * p], b = xs[2 * p + 1];
        __nv_bfloat162 hb2 = __floats2bfloat162_rn(a, b);
        float ha = __bfloat162float(__low2bfloat16(hb2));
        float hbv = __bfloat162float(__high2bfloat16(hb2));
        hw[p] = *(uint32_t*)&hb2;
        __nv_bfloat162 lb2 = __floats2bfloat162_rn(a - ha, b - hbv);
        lw[p] = *(uint32_t*)&lb2;
    }
    *(uint4*)dhi = make_uint4(hw[0], hw[1], hw[2], hw[3]);
    *(uint4*)dlo = make_uint4(lw[0], lw[1], lw[2], lw[3]);
}
__device__ __forceinline__ void split_sts4(const float* xs, char* dhi, char* dlo) {
    uint32_t hw[2], lw[2];
    #pragma unroll
    for (int p = 0; p < 2; p++) {
        float a = xs[2 * p], b = xs[2 * p + 1];
        __nv_bfloat162 hb2 = __floats2bfloat162_rn(a, b);
        float ha = __bfloat162float(__low2bfloat16(hb2));
        float hbv = __bfloat162float(__high2bfloat16(hb2));
        hw[p] = *(uint32_t*)&hb2;
        __nv_bfloat162 lb2 = __floats2bfloat162_rn(a - ha, b - hbv);
        lw[p] = *(uint32_t*)&lb2;
    }
    *(uint2*)dhi = make_uint2(hw[0], hw[1]);
    *(uint2*)dlo = make_uint2(lw[0], lw[1]);
}
__device__ __forceinline__ void load8(float* d, const float* s) {
    float4 u = *(const float4*)s, v = *(const float4*)(s + 4);
    d[0] = u.x; d[1] = u.y; d[2] = u.z; d[3] = u.w;
    d[4] = v.x; d[5] = v.y; d[6] = v.z; d[7] = v.w;
}
__device__ __forceinline__ void load4(float* d, const float* s) {
    float4 u = *(const float4*)s;
    d[0] = u.x; d[1] = u.y; d[2] = u.z; d[3] = u.w;
}

// ===== smem layout =====
#define A_LD_B    48
#define A_PLANE   (128 * A_LD_B)       // 6144
#define B1_LD_B   272
#define B1_PLANE  (16 * B1_LD_B)       // 4352
#define BUF1_B    (2 * A_PLANE + 2 * B1_PLANE)  // 20992 per buffer
#define SMEM1_BYTES (2 * BUF1_B)       // 41984 (k1, double-buffered)
#define BUF2_B    (4 * A_PLANE)        // 24576 per buffer
#define SMEM2_BYTES (2 * BUF2_B)       // 49152 (k2, double-buffered; 48KB static limit)

// ================= k0: pre-split W0 / W2 to bf16 hi/lo =================
// 256 blocks x 256 threads; bid<128 -> W0, else W2; 2048 elems per block.
__global__ __launch_bounds__(256) void k0(const float* __restrict__ Wo) {
    const int bid = blockIdx.x, tid = threadIdx.x;
    const float* src = (bid < 128) ? Wo : (Wo + (size_t)2 * D * D);
    __nv_bfloat16* dh = (bid < 128) ? g_W0h : g_W2h;
    __nv_bfloat16* dl = (bid < 128) ? g_W0l : g_W2l;
    const size_t off = (size_t)(bid & 127) * 2048 + (size_t)tid * 8;
    float xs[8];
    load8(xs, src + off);
    split_sts8(xs, (char*)(dh + off), (char*)(dl + off));
}

// ================= mm core 1: C[128,128] = A[bm:,512] @ W[512, bn:] (+bias) =================
// A fp32 (split at stage time); W pre-split bf16 hi/lo (K-major). Double-buffered.
__device__ __forceinline__ void mm_core1(const float* __restrict__ A,
                                         const __nv_bfloat16* __restrict__ Wh,
                                         const __nv_bfloat16* __restrict__ Wl,
                                         float* __restrict__ C,
                                         const float* __restrict__ bias,
                                         int bm, int bn, char* smem) {
    const int tid = threadIdx.x, lane = tid & 31, wid = tid >> 5;
    const int wm = wid >> 2, wn = wid & 3;
    const uint32_t sU = smem_u32(smem);

    const int arow = tid >> 1, ah = (tid & 1) * 8;
    const int bk = tid >> 4, bn8 = (tid & 15) * 8;
    const float* aSrc = A + (size_t)(bm + arow) * 512 + ah;
    const __nv_bfloat16* bhSrc = Wh + (size_t)bk * 512 + bn + bn8;
    const __nv_bfloat16* blSrc = Wl + (size_t)bk * 512 + bn + bn8;

    float acc[4][4][4];
    #pragma unroll
    for (int mt = 0; mt < 4; mt++)
        #pragma unroll
        for (int nt = 0; nt < 4; nt++)
            #pragma unroll
            for (int cc = 0; cc < 4; cc++) acc[mt][nt][cc] = 0.f;

    float pa[8];
    uint4 pbh, pbl;
    load8(pa, aSrc);
    pbh = *(const uint4*)bhSrc;
    pbl = *(const uint4*)blSrc;
    {
        char* b0 = smem;
        split_sts8(pa, b0 + arow * A_LD_B + ah * 2, b0 + A_PLANE + arow * A_LD_B + ah * 2);
        *(uint4*)(b0 + 2 * A_PLANE + bk * B1_LD_B + bn8 * 2) = pbh;
        *(uint4*)(b0 + 2 * A_PLANE + B1_PLANE + bk * B1_LD_B + bn8 * 2) = pbl;
    }
    __syncthreads();

    for (int kt = 0; kt < 32; kt++) {
        const int cb = kt & 1;
        const bool more = (kt < 31);
        if (more) {
            load8(pa, aSrc + (kt + 1) * 16);
            pbh = *(const uint4*)(bhSrc + (size_t)(kt + 1) * 16 * 512);
            pbl = *(const uint4*)(blSrc + (size_t)(kt + 1) * 16 * 512);
        }
        const uint32_t base = sU + cb * BUF1_B;
        const uint32_t aHiU = base, aLoU = base + A_PLANE;
        const uint32_t bHiU = base + 2 * A_PLANE, bLoU = bHiU + B1_PLANE;
        uint32_t bfh[4][2], bfl[4][2];
        #pragma unroll
        for (int nt = 0; nt < 4; nt++) {
            uint32_t off = (lane & 15) * B1_LD_B + (wn * 32 + nt * 8) * 2;
            ldsm_x2_t(bfh[nt], bHiU + off);
            ldsm_x2_t(bfl[nt], bLoU + off);
        }
        #pragma unroll
        for (int mt = 0; mt < 4; mt++) {
            uint32_t aoff = (wm * 64 + mt * 16 + (lane & 15)) * A_LD_B + (lane >> 4) * 16;
            uint32_t fh[4], fl[4];
            ldsm_x4(fh, aHiU + aoff);
            ldsm_x4(fl, aLoU + aoff);
            #pragma unroll
            for (int nt = 0; nt < 4; nt++) {
                mma16816(acc[mt][nt], fh, bfh[nt]);
                mma16816(acc[mt][nt], fh, bfl[nt]);
                mma16816(acc[mt][nt], fl, bfh[nt]);
            }
        }
        if (more) {
            char* nb = smem + (cb ^ 1) * BUF1_B;
            split_sts8(pa, nb + arow * A_LD_B + ah * 2, nb + A_PLANE + arow * A_LD_B + ah * 2);
            *(uint4*)(nb + 2 * A_PLANE + bk * B1_LD_B + bn8 * 2) = pbh;
            *(uint4*)(nb + 2 * A_PLANE + B1_PLANE + bk * B1_LD_B + bn8 * 2) = pbl;
            __syncthreads();
        }
    }

    #pragma unroll
    for (int mt = 0; mt < 4; mt++) {
        #pragma unroll
        for (int nt = 0; nt < 4; nt++) {
            int row = bm + wm * 64 + mt * 16 + (lane >> 2);
            int col = bn + wn * 32 + nt * 8 + 2 * (lane & 3);
            float b0 = bias ? bias[col] : 0.f;
            float b1 = bias ? bias[col + 1] : 0.f;
            float* c0 = C + (size_t)row * 512 + col;
            c0[0] = acc[mt][nt][0] + b0;
            c0[1] = acc[mt][nt][1] + b1;
            float* c1 = C + (size_t)(row + 8) * 512 + col;
            c1[0] = acc[mt][nt][2] + b0;
            c1[1] = acc[mt][nt][3] + b1;
        }
    }
}

// ================= mm core 2: einsum 128x128 tile, 512 threads, double-buffered =================
// C[t][s] = sum_d (P[t,n,d]+embproj[tg0,d]+qproj[tg1,n,d]) * srcE[s,n,d]
__device__ __forceinline__ void mm_core2(const int* __restrict__ tgt,
                                         const float* __restrict__ srcE,
                                         const unsigned char* __restrict__ mask,
                                         float* __restrict__ out_obj,
                                         int n, char* smem) {
    const int tid = threadIdx.x, lane = tid & 31, wid = tid >> 5;
    const int wm = wid >> 2, wn = wid & 3;
    const uint32_t sU = smem_u32(smem);

    const int srow = tid >> 2;
    const int sk   = (tid & 3) * 4;

    const int tp = (srow + 1) & (TT - 1);
    const int* tg = tgt + ((size_t)tp * NN + n) * 3;
    const float* pA = g_P + ((size_t)srow * NN + n) * 512 + sk;
    const float* pE = g_embproj + (size_t)tg[0] * 512 + sk;
    const float* pQ = g_qproj + ((size_t)tg[1] * NN + n) * 512 + sk;
    const float* pB = srcE + ((size_t)srow * NN + n) * 512 + sk;

    float acc[2][4][4];
    #pragma unroll
    for (int mt = 0; mt < 2; mt++)
        #pragma unroll
        for (int nt = 0; nt < 4; nt++)
            #pragma unroll
            for (int cc = 0; cc < 4; cc++) acc[mt][nt][cc] = 0.f;

    float pa[4], pb[4];
    {
        float xa[4], xe[4], xq[4];
        load4(xa, pA); load4(xe, pE); load4(xq, pQ);
        #pragma unroll
        for (int i = 0; i < 4; i++) pa[i] = (xa[i] + xe[i]) + xq[i];
        load4(pb, pB);
    }
    {
        char* b0 = smem;
        split_sts4(pa, b0 + srow * A_LD_B + sk * 2, b0 + A_PLANE + srow * A_LD_B + sk * 2);
        split_sts4(pb, b0 + 2 * A_PLANE + srow * A_LD_B + sk * 2,
                   b0 + 3 * A_PLANE + srow * A_LD_B + sk * 2);
    }
    __syncthreads();

    for (int kt = 0; kt < 32; kt++) {
        const int cb = kt & 1;
        const bool more = (kt < 31);
        if (more) {
            int k0 = (kt + 1) * 16;
            float xa[4], xe[4], xq[4];
            load4(xa, pA + k0); load4(xe, pE + k0); load4(xq, pQ + k0);
            #pragma unroll
            for (int i = 0; i < 4; i++) pa[i] = (xa[i] + xe[i]) + xq[i];
            load4(pb, pB + k0);
        }
        const uint32_t base = sU + cb * BUF2_B;
        const uint32_t aHiU = base, aLoU = base + A_PLANE;
        const uint32_t bHiU = base + 2 * A_PLANE, bLoU = base + 3 * A_PLANE;
        uint32_t bfh[4][2], bfl[4][2];
        #pragma unroll
        for (int nt = 0; nt < 4; nt++) {
            uint32_t off = (wn * 32 + nt * 8 + (lane & 7)) * A_LD_B + ((lane >> 3) & 1) * 16;
            ldsm_x2(bfh[nt], bHiU + off);
            ldsm_x2(bfl[nt], bLoU + off);
        }
        #pragma unroll
        for (int mt = 0; mt < 2; mt++) {
            uint32_t aoff = (wm * 32 + mt * 16 + (lane & 15)) * A_LD_B + (lane >> 4) * 16;
            uint32_t fh[4], fl[4];
            ldsm_x4(fh, aHiU + aoff);
            ldsm_x4(fl, aLoU + aoff);
            #pragma unroll
            for (int nt = 0; nt < 4; nt++) {
                mma16816(acc[mt][nt], fh, bfh[nt]);
                mma16816(acc[mt][nt], fh, bfl[nt]);
                mma16816(acc[mt][nt], fl, bfh[nt]);
            }
        }
        if (more) {
            char* nb = smem + (cb ^ 1) * BUF2_B;
            split_sts4(pa, nb + srow * A_LD_B + sk * 2, nb + A_PLANE + srow * A_LD_B + sk * 2);
            split_sts4(pb, nb + 2 * A_PLANE + srow * A_LD_B + sk * 2,
                       nb + 3 * A_PLANE + srow * A_LD_B + sk * 2);
            __syncthreads();
        }
    }

    const float NEG_INF = __int_as_float(0xff800000);
    #pragma unroll
    for (int mt = 0; mt < 2; mt++) {
        #pragma unroll
        for (int nt = 0; nt < 4; nt++) {
            int t = wm * 32 + mt * 16 + (lane >> 2);
            int s = wn * 32 + nt * 8 + 2 * (lane & 3);
            unsigned char m0 = mask[n * SS + s], m1 = mask[n * SS + s + 1];
            float* o0 = out_obj + ((size_t)t * NN + n) * SS + s;
            o0[0] = m0 ? NEG_INF : acc[mt][nt][0];
            o0[1] = m1 ? NEG_INF : acc[mt][nt][1];
            float* o1 = out_obj + ((size_t)(t + 8) * NN + n) * SS + s;
            o1[0] = m0 ? NEG_INF : acc[mt][nt][2];
            o1[1] = m1 ? NEG_INF : acc[mt][nt][3];
        }
    }
}

// ================= k1: 466 blocks x 256 threads =================
__global__ __launch_bounds__(256, 2) void k1(const float* __restrict__ dec,
                                             const float* __restrict__ srcE,
                                             const float* __restrict__ emb,
                                             const float* __restrict__ Wo,
                                             const float* __restrict__ bo,
                                             const float* __restrict__ Wd) {
    __shared__ __align__(16) char smem[SMEM1_BYTES];
    const int bid = blockIdx.x, tid = threadIdx.x;

    if (bid < 256) {
        mm_core1(dec, g_W0h, g_W0l, g_P, bo, (bid >> 2) * 128, (bid & 3) * 128, smem);
    } else if (bid < 268) {
        int q = bid - 256;
        mm_core1(srcE, g_W2h, g_W2l, g_qproj, (const float*)0,
                 (q >> 2) * 128, (q & 3) * 128, smem);
    } else if (bid < 274) {
        int i = bid - 268;
        float* e = (float*)smem;
        e[tid]       = emb[i * D + tid];
        e[tid + 256] = emb[i * D + tid + 256];
        __syncthreads();
        #pragma unroll
        for (int half = 0; half < 2; half++) {
            int c = tid + half * 256;
            float acc = 0.f;
            const float* wb = Wo + (size_t)D * D + c;
            #pragma unroll 8
            for (int k = 0; k < D; k++) acc += e[k] * wb[(size_t)k * D];
            g_embproj[i * D + c] = acc;
        }
        if (tid < 5) {
            float a = 0.f;
            const float* wd = Wd + (size_t)D * 5 + tid;
            for (int k = 0; k < D; k++) a += e[k] * wd[k * 5];
            g_embdir[i * 5 + tid] = a;
        }
    } else {
        const int g  = tid >> 7;
        const int lt = tid & 127;
        const int r  = (bid - 274) * 2 + g;
        float acc[10];
        #pragma unroll
        for (int j = 0; j < 10; j++) acc[j] = 0.f;
        const float* row = srcE + (size_t)r * D;
        for (int k = lt; k < D; k += 128) {
            float v = row[k];
            const float* w2 = Wd + (size_t)(2 * D + k) * 5;
            const float* w3 = Wd + (size_t)(3 * D + k) * 5;
            #pragma unroll
            for (int j = 0; j < 5; j++) {
                acc[j]     += v * w2[j];
                acc[5 + j] += v * w3[j];
            }
        }
        #pragma unroll
        for (int off = 16; off; off >>= 1)
            #pragma unroll
            for (int j = 0; j < 10; j++)
                acc[j] += __shfl_down_sync(0xffffffffu, acc[j], off);
        float* red = (float*)smem;
        const int w = tid >> 5, lane = tid & 31;
        if (lane == 0)
            #pragma unroll
            for (int j = 0; j < 10; j++) red[w * 10 + j] = acc[j];
        __syncthreads();
        if (lt < 10) {
            int wb = g * 4;
            float s = red[(wb + 0) * 10 + lt] + red[(wb + 1) * 10 + lt]
                    + red[(wb + 2) * 10 + lt] + red[(wb + 3) * 10 + lt];
            if (lt < 5) g_qdir[r * 5 + lt] = s;
            else        g_rdir[r * 5 + (lt - 5)] = s;
        }
    }
}

// ================= k2: 104 blocks x 512 threads =================
//  [0,64)   einsum per n, 16-warp HMMA tile, double-buffered
//  [64,104) typedir (205 rows each)
__global__ __launch_bounds__(512, 1) void k2(const float* __restrict__ srcE,
                                             const unsigned char* __restrict__ mask,
                                             const int* __restrict__ tgt,
                                             const float* __restrict__ dec,
                                             const float* __restrict__ Wt,
                                             const float* __restrict__ bt,
                                             const float* __restrict__ Wd,
                                             const float* __restrict__ bd,
                                             float* __restrict__ out_type,
                                             float* __restrict__ out_obj,
                                             float* __restrict__ out_dir) {
    __shared__ __align__(16) char smem[SMEM2_BYTES];
    const int bid = blockIdx.x, tid = threadIdx.x;

    if (bid < 64) {
        mm_core2(tgt, srcE, mask, out_obj, bid, smem);
    } else {
        float* sW = (float*)smem;                          // 512 x 11
        for (int i = tid; i < D * 6; i += 512) {
            int k = i / 6, c = i % 6;
            sW[k * 11 + c] = Wt[i];
        }
        for (int i = tid; i < D * 5; i += 512) {
            int k = i / 5, c = i % 5;
            sW[k * 11 + 6 + c] = Wd[i];
        }
        __syncthreads();
        const int w = tid >> 5, lane = tid & 31;
        const int r0 = (bid - 64) * 205;
        int rend = r0 + 205;
        if (rend > 8192) rend = 8192;
        for (int r = r0 + w; r < rend; r += 16) {
            const float* drow = dec + (size_t)r * D;
            float acc[11];
            #pragma unroll
            for (int c = 0; c < 11; c++) acc[c] = 0.f;
            #pragma unroll 4
            for (int u = 0; u < 16; u++) {
                int k = u * 32 + lane;
                float v = drow[k];
                const float* wp = &sW[k * 11];
                #pragma unroll
                for (int c = 0; c < 11; c++) acc[c] += v * wp[c];
            }
            #pragma unroll
            for (int off = 16; off; off >>= 1)
                #pragma unroll
                for (int c = 0; c < 11; c++)
                    acc[c] += __shfl_xor_sync(0xffffffffu, acc[c], off);
            if (lane < 11) {
                int t = r >> 6, n = r & 63;
                int tp = (t + 1) & (TT - 1);
                const int* tg = tgt + ((size_t)tp * NN + n) * 3;
                if (lane < 6) {
                    out_type[(size_t)r * 6 + lane] = acc[lane] + bt[lane];
                } else {
                    int j = lane - 6;
                    out_dir[(size_t)r * 5 + j] = acc[lane] + bd[j]
                        + g_embdir[tg[0] * 5 + j]
                        + g_qdir[((size_t)tg[1] * NN + n) * 5 + j]
                        + g_rdir[((size_t)tg[2] * NN + n) * 5 + j];
                }
            }
        }
    }
}

// ================= launch =================
extern "C" void kernel_launch(void* const* d_in, const int* in_sizes, int n_in,
                              void* d_out, int out_size) {
    const float*         dec  = (const float*)d_in[0];   // (T,N,D)
    const int*           tgt  = (const int*)d_in[1];     // (T,N,3)
    const float*         srcE = (const float*)d_in[2];   // (S,N,D)
    const unsigned char* mask = (const unsigned char*)d_in[3]; // (N,S) bool
    const float*         emb  = (const float*)d_in[4];   // (6,D)
    const float*         Wt   = (const float*)d_in[5];   // (D,6)
    const float*         bt   = (const float*)d_in[6];   // (6,)
    const float*         Wo   = (const float*)d_in[7];   // (3D,D)
    const float*         bo   = (const float*)d_in[8];   // (D,)
    const float*         Wd   = (const float*)d_in[9];   // (4D,5)
    const float*         bd   = (const float*)d_in[10];  // (5,)

    float* out      = (float*)d_out;
    float* out_type = out;                                    // (T,N,6)
    float* out_obj  = out + (size_t)TT * NN * 6;              // (T,N,S)
    float* out_dir  = out + (size_t)TT * NN * 6 + (size_t)TT * NN * SS; // (T,N,5)

    k0<<<256, 256>>>(Wo);
    k1<<<466, 256>>>(dec, srcE, emb, Wo, bo, Wd);
    k2<<<104, 512>>>(srcE, mask, tgt, dec, Wt, bt, Wd, bd,
                     out_type, out_obj, out_dir);
}